// round 1
// baseline (speedup 1.0000x reference)
#include <cuda_runtime.h>

#define BSZ 2
#define NQ 10000
#define EDIM 256
#define NH 8
#define NL 4
#define NP 8
#define DH 32               // EDIM / NH
#define LEN_VAL 13294       // 100*100 + 50*50 + 25*25 + 13*13

// ---------------- scratch (device globals: allocation-free) ----------------
__device__ float g_v[(size_t)BSZ * LEN_VAL * EDIM];          // projected value  [b][pos][e]
__device__ float g_q[(size_t)BSZ * NQ * EDIM];               // query + query_pos
__device__ float g_off[(size_t)BSZ * NQ * NH * NL * NP * 2]; // sampling offsets
__device__ float g_attnl[(size_t)BSZ * NQ * EDIM];           // attention logits
__device__ float g_mid[(size_t)BSZ * NQ * EDIM];             // pre-out-proj result

__constant__ int c_Hs[NL]    = {100, 50, 25, 13};
__constant__ int c_Ws[NL]    = {100, 50, 25, 13};
__constant__ int c_start[NL] = {0, 10000, 12500, 13125};

// ---------------- elementwise: q = query + query_pos ----------------
__global__ void add_pos_kernel(const float4* __restrict__ a,
                               const float4* __restrict__ b,
                               float4* __restrict__ o, int n4) {
    int i = blockIdx.x * blockDim.x + threadIdx.x;
    if (i < n4) {
        float4 x = a[i], y = b[i];
        o[i] = make_float4(x.x + y.x, x.y + y.y, x.z + y.z, x.w + y.w);
    }
}

// ---------------- tiled SGEMM: C[M,N] = A[M,K] @ B[K,N] + bias[N] ----------------
// BM=64, BN=64, BK=16, 256 threads, 4x4 per thread.
__global__ void sgemm_bias_kernel(const float* __restrict__ A,
                                  const float* __restrict__ B,
                                  const float* __restrict__ bias,
                                  float* __restrict__ C,
                                  int M, int N, int K) {
    const int BM = 64, BN = 64, BK = 16;
    __shared__ float As[BK][BM];
    __shared__ float Bs[BK][BN];

    int block_row = blockIdx.y * BM;
    int block_col = blockIdx.x * BN;
    int tid = threadIdx.x;
    int tr = tid >> 4;          // 0..15
    int tc = tid & 15;          // 0..15

    float acc[4][4];
#pragma unroll
    for (int i = 0; i < 4; i++)
#pragma unroll
        for (int j = 0; j < 4; j++) acc[i][j] = 0.f;

    for (int k0 = 0; k0 < K; k0 += BK) {
        // load A tile (64 x 16), transpose into As[k][m]
#pragma unroll
        for (int i = tid; i < BM * BK; i += 256) {
            int m = i >> 4;
            int kk = i & 15;
            int gm = block_row + m;
            float v = 0.f;
            if (gm < M) v = A[(size_t)gm * K + k0 + kk];
            As[kk][m] = v;
        }
        // load B tile (16 x 64)
#pragma unroll
        for (int i = tid; i < BK * BN; i += 256) {
            int kk = i >> 6;
            int nn = i & 63;
            int gn = block_col + nn;
            float v = 0.f;
            if (gn < N) v = B[(size_t)(k0 + kk) * N + gn];
            Bs[kk][nn] = v;
        }
        __syncthreads();

#pragma unroll
        for (int kk = 0; kk < BK; kk++) {
            float a[4], bb[4];
#pragma unroll
            for (int j = 0; j < 4; j++) a[j] = As[kk][tr * 4 + j];
#pragma unroll
            for (int j = 0; j < 4; j++) bb[j] = Bs[kk][tc * 4 + j];
#pragma unroll
            for (int x = 0; x < 4; x++)
#pragma unroll
                for (int y = 0; y < 4; y++) acc[x][y] += a[x] * bb[y];
        }
        __syncthreads();
    }

#pragma unroll
    for (int x = 0; x < 4; x++) {
        int gm = block_row + tr * 4 + x;
        if (gm >= M) continue;
#pragma unroll
        for (int y = 0; y < 4; y++) {
            int gn = block_col + tc * 4 + y;
            if (gn < N) C[(size_t)gm * N + gn] = acc[x][y] + bias[gn];
        }
    }
}

// ---------------- deformable sampling ----------------
// One warp per (b, n, h). Lane i owns sample i (l = i>>3, p = i&7):
// computes its location, corner offsets/weights, softmax weight.
// Then the warp loops over the 32 samples; each lane gathers channel d=lane
// of the 4 corners (coalesced 128B per corner) and accumulates.
__global__ void sample_kernel(const float* __restrict__ ref) {
    int gw = (blockIdx.x * blockDim.x + threadIdx.x) >> 5;
    int lane = threadIdx.x & 31;
    if (gw >= BSZ * NQ * NH) return;

    int h = gw & (NH - 1);
    int n = (gw >> 3) % NQ;
    int b = gw / (NQ * NH);

    int l = lane >> 3;
    int p = lane & 7;
    int Hs = c_Hs[l], Ws = c_Ws[l];

    long qrow = (long)b * NQ + n;

    int ocol = ((h * NL + l) * NP + p) * 2;
    float ox = g_off[qrow * (NH * NL * NP * 2) + ocol];
    float oy = g_off[qrow * (NH * NL * NP * 2) + ocol + 1];
    float rx = ref[(qrow * NL + l) * 2 + 0];
    float ry = ref[(qrow * NL + l) * 2 + 1];

    // pixel coords: x = ref_x * Ws + off_x - 0.5  (align_corners=False)
    float x = rx * (float)Ws + ox - 0.5f;
    float y = ry * (float)Hs + oy - 0.5f;

    float fx0 = floorf(x), fy0 = floorf(y);
    int x0 = (int)fx0, y0 = (int)fy0;
    float wx1 = x - fx0, wy1 = y - fy0;
    float wx0 = 1.f - wx1, wy0 = 1.f - wy1;

    // softmax over the 32 (l,p) logits of this (b,n,h)
    float logit = g_attnl[qrow * EDIM + h * DH + lane];
    float m = logit;
#pragma unroll
    for (int o = 16; o; o >>= 1) m = fmaxf(m, __shfl_xor_sync(0xFFFFFFFFu, m, o));
    float ex = __expf(logit - m);
    float s = ex;
#pragma unroll
    for (int o = 16; o; o >>= 1) s += __shfl_xor_sync(0xFFFFFFFFu, s, o);
    float aw = ex / s;

    int x1 = x0 + 1, y1 = y0 + 1;
    bool vx0 = (x0 >= 0) && (x0 < Ws);
    bool vx1 = (x1 >= 0) && (x1 < Ws);
    bool vy0 = (y0 >= 0) && (y0 < Hs);
    bool vy1 = (y1 >= 0) && (y1 < Hs);

    int base = (b * LEN_VAL + c_start[l]) * EDIM + h * DH;

    int p00 = (vy0 && vx0) ? (y0 * Ws + x0) : 0;
    int p01 = (vy0 && vx1) ? (y0 * Ws + x1) : 0;
    int p10 = (vy1 && vx0) ? (y1 * Ws + x0) : 0;
    int p11 = (vy1 && vx1) ? (y1 * Ws + x1) : 0;

    float w00 = (vy0 && vx0) ? aw * wx0 * wy0 : 0.f;
    float w01 = (vy0 && vx1) ? aw * wx1 * wy0 : 0.f;
    float w10 = (vy1 && vx0) ? aw * wx0 * wy1 : 0.f;
    float w11 = (vy1 && vx1) ? aw * wx1 * wy1 : 0.f;

    int o00 = base + p00 * EDIM;
    int o01 = base + p01 * EDIM;
    int o10 = base + p10 * EDIM;
    int o11 = base + p11 * EDIM;

    float acc = 0.f;
#pragma unroll 4
    for (int sIdx = 0; sIdx < 32; sIdx++) {
        int a0 = __shfl_sync(0xFFFFFFFFu, o00, sIdx);
        int a1 = __shfl_sync(0xFFFFFFFFu, o01, sIdx);
        int a2 = __shfl_sync(0xFFFFFFFFu, o10, sIdx);
        int a3 = __shfl_sync(0xFFFFFFFFu, o11, sIdx);
        float u0 = __shfl_sync(0xFFFFFFFFu, w00, sIdx);
        float u1 = __shfl_sync(0xFFFFFFFFu, w01, sIdx);
        float u2 = __shfl_sync(0xFFFFFFFFu, w10, sIdx);
        float u3 = __shfl_sync(0xFFFFFFFFu, w11, sIdx);
        float v0 = g_v[a0 + lane];
        float v1 = g_v[a1 + lane];
        float v2 = g_v[a2 + lane];
        float v3 = g_v[a3 + lane];
        acc += u0 * v0 + u1 * v1 + u2 * v2 + u3 * v3;
    }
    g_mid[qrow * EDIM + h * DH + lane] = acc;
}

// ---------------- launch ----------------
extern "C" void kernel_launch(void* const* d_in, const int* in_sizes, int n_in,
                              void* d_out, int out_size) {
    const float* query   = (const float*)d_in[0];
    const float* value   = (const float*)d_in[1];
    const float* qpos    = (const float*)d_in[2];
    const float* refpts  = (const float*)d_in[3];
    // d_in[4] = spatial_shapes (compile-time known)
    const float* W_off   = (const float*)d_in[5];
    const float* b_off   = (const float*)d_in[6];
    const float* W_attn  = (const float*)d_in[7];
    const float* b_attn  = (const float*)d_in[8];
    const float* W_val   = (const float*)d_in[9];
    const float* b_val   = (const float*)d_in[10];
    const float* W_out   = (const float*)d_in[11];
    const float* b_out   = (const float*)d_in[12];
    float* out = (float*)d_out;

    float* vq;    cudaGetSymbolAddress((void**)&vq, g_q);
    float* vv;    cudaGetSymbolAddress((void**)&vv, g_v);
    float* voff;  cudaGetSymbolAddress((void**)&voff, g_off);
    float* vattn; cudaGetSymbolAddress((void**)&vattn, g_attnl);
    float* vmid;  cudaGetSymbolAddress((void**)&vmid, g_mid);

    // 1) q = query + query_pos
    {
        int n4 = BSZ * NQ * EDIM / 4;
        add_pos_kernel<<<(n4 + 255) / 256, 256>>>(
            (const float4*)query, (const float4*)qpos, (float4*)vq, n4);
    }
    // 2) v = value @ W_val + b_val   (M = BSZ*LEN_VAL)
    {
        int M = BSZ * LEN_VAL, N = EDIM, K = EDIM;
        dim3 grid(N / 64, (M + 63) / 64);
        sgemm_bias_kernel<<<grid, 256>>>(value, W_val, b_val, vv, M, N, K);
    }
    // 3) off = q @ W_off + b_off     (N = 512)
    {
        int M = BSZ * NQ, N = NH * NL * NP * 2, K = EDIM;
        dim3 grid(N / 64, (M + 63) / 64);
        sgemm_bias_kernel<<<grid, 256>>>(vq, W_off, b_off, voff, M, N, K);
    }
    // 4) attn logits = q @ W_attn + b_attn
    {
        int M = BSZ * NQ, N = EDIM, K = EDIM;
        dim3 grid(N / 64, (M + 63) / 64);
        sgemm_bias_kernel<<<grid, 256>>>(vq, W_attn, b_attn, vattn, M, N, K);
    }
    // 5) deformable sampling -> g_mid
    {
        int warps = BSZ * NQ * NH;               // 160000
        int blocks = (warps * 32 + 255) / 256;   // 20000
        sample_kernel<<<blocks, 256>>>(refpts);
    }
    // 6) out = g_mid @ W_out + b_out
    {
        int M = BSZ * NQ, N = EDIM, K = EDIM;
        dim3 grid(N / 64, (M + 63) / 64);
        sgemm_bias_kernel<<<grid, 256>>>(vmid, W_out, b_out, out, M, N, K);
    }
}

// round 2
// speedup vs baseline: 2.3985x; 2.3985x over previous
#include <cuda_runtime.h>
#include <cuda_bf16.h>
#include <cstdint>

#define BSZ 2
#define NQ 10000
#define EDIM 256
#define NH 8
#define NL 4
#define NP 8
#define DH 32               // EDIM / NH
#define LEN_VAL 13294       // 100*100 + 50*50 + 25*25 + 13*13

// ---------------- scratch (device globals: allocation-free) ----------------
__device__ float g_v[(size_t)BSZ * LEN_VAL * EDIM];          // projected value  [b][pos][e]
__device__ float g_q[(size_t)BSZ * NQ * EDIM];               // query + query_pos
__device__ float g_off[(size_t)BSZ * NQ * NH * NL * NP * 2]; // sampling offsets
__device__ float g_attnl[(size_t)BSZ * NQ * EDIM];           // attention logits
__device__ float g_mid[(size_t)BSZ * NQ * EDIM];             // pre-out-proj result

// bf16 hi/lo split weights: [W_val 256x256][W_off 256x512][W_attn 256x256][W_out 256x256]
#define WOFF_VAL  0
#define WOFF_OFF  65536
#define WOFF_ATTN 196608
#define WOFF_OUT  262144
#define WTOTAL    327680
__device__ __nv_bfloat16 g_Wh[WTOTAL];
__device__ __nv_bfloat16 g_Wl[WTOTAL];

__constant__ int c_Hs[NL]    = {100, 50, 25, 13};
__constant__ int c_Ws[NL]    = {100, 50, 25, 13};
__constant__ int c_start[NL] = {0, 10000, 12500, 13125};

// ---------------- helpers ----------------
__device__ __forceinline__ uint32_t pack_bf16(__nv_bfloat16 a, __nv_bfloat16 b) {
    __nv_bfloat162 t = __halves2bfloat162(a, b);   // a = low half
    return *reinterpret_cast<uint32_t*>(&t);
}

__device__ __forceinline__ void split2(float x0, float x1, uint32_t& hi, uint32_t& lo) {
    __nv_bfloat16 h0 = __float2bfloat16(x0);
    __nv_bfloat16 h1 = __float2bfloat16(x1);
    float r0 = x0 - __bfloat162float(h0);
    float r1 = x1 - __bfloat162float(h1);
    hi = pack_bf16(h0, h1);
    lo = pack_bf16(__float2bfloat16(r0), __float2bfloat16(r1));
}

__device__ __forceinline__ void ldm_x4(uint32_t& r0, uint32_t& r1, uint32_t& r2, uint32_t& r3,
                                       uint32_t addr) {
    asm volatile("ldmatrix.sync.aligned.m8n8.x4.shared.b16 {%0,%1,%2,%3}, [%4];"
                 : "=r"(r0), "=r"(r1), "=r"(r2), "=r"(r3) : "r"(addr));
}

__device__ __forceinline__ void ldm_x4_trans(uint32_t& r0, uint32_t& r1, uint32_t& r2, uint32_t& r3,
                                             uint32_t addr) {
    asm volatile("ldmatrix.sync.aligned.m8n8.x4.trans.shared.b16 {%0,%1,%2,%3}, [%4];"
                 : "=r"(r0), "=r"(r1), "=r"(r2), "=r"(r3) : "r"(addr));
}

__device__ __forceinline__ void mma_bf16(float* d, const uint32_t* a, const uint32_t* b) {
    asm volatile("mma.sync.aligned.m16n8k16.row.col.f32.bf16.bf16.f32 "
                 "{%0,%1,%2,%3},{%4,%5,%6,%7},{%8,%9},{%0,%1,%2,%3};"
                 : "+f"(d[0]), "+f"(d[1]), "+f"(d[2]), "+f"(d[3])
                 : "r"(a[0]), "r"(a[1]), "r"(a[2]), "r"(a[3]), "r"(b[0]), "r"(b[1]));
}

// ---------------- weight split kernel ----------------
__global__ void split_weights_kernel(const float* __restrict__ W_val,
                                     const float* __restrict__ W_off,
                                     const float* __restrict__ W_attn,
                                     const float* __restrict__ W_out) {
    int i = blockIdx.x * blockDim.x + threadIdx.x;
    if (i >= WTOTAL) return;
    float x;
    if (i < WOFF_OFF)        x = W_val[i - WOFF_VAL];
    else if (i < WOFF_ATTN)  x = W_off[i - WOFF_OFF];
    else if (i < WOFF_OUT)   x = W_attn[i - WOFF_ATTN];
    else                     x = W_out[i - WOFF_OUT];
    __nv_bfloat16 h = __float2bfloat16(x);
    g_Wh[i] = h;
    g_Wl[i] = __float2bfloat16(x - __bfloat162float(h));
}

// ---------------- elementwise: q = query + query_pos ----------------
__global__ void add_pos_kernel(const float4* __restrict__ a,
                               const float4* __restrict__ b,
                               float4* __restrict__ o, int n4) {
    int i = blockIdx.x * blockDim.x + threadIdx.x;
    if (i < n4) {
        float4 x = a[i], y = b[i];
        o[i] = make_float4(x.x + y.x, x.y + y.y, x.z + y.z, x.w + y.w);
    }
}

// ---------------- bf16x3 tensor-core GEMM ----------------
// C[M,N] = A[M,K](fp32, split on the fly) @ B[K,N](pre-split bf16 hi/lo) + bias
// BM=128, BN=128, BK=32, 512 threads (16 warps, 4x4), warp tile 32x32.
#define SA_STRIDE 40     // halfs per A smem row (32 data + 8 pad)
#define SB_STRIDE 136    // halfs per B smem row (128 data + 8 pad)
#define SA_STAGE  (128 * SA_STRIDE)
#define SB_STAGE  (32 * SB_STRIDE)
#define GEMM_SMEM ((2 * SA_STAGE * 2 + 2 * SB_STAGE * 2) * 2)  // bytes = 75776

__global__ void __launch_bounds__(512, 1)
gemm_bf16x3_kernel(const float* __restrict__ A,
                   const __nv_bfloat16* __restrict__ Bh,
                   const __nv_bfloat16* __restrict__ Bl,
                   const float* __restrict__ bias,
                   float* __restrict__ C,
                   int M, int N, int K) {
    extern __shared__ char smem_raw[];
    __nv_bfloat16* sAh = (__nv_bfloat16*)smem_raw;        // [2][128][SA_STRIDE]
    __nv_bfloat16* sAl = sAh + 2 * SA_STAGE;
    __nv_bfloat16* sBh = sAl + 2 * SA_STAGE;              // [2][32][SB_STRIDE]
    __nv_bfloat16* sBl = sBh + 2 * SB_STAGE;

    const int tid  = threadIdx.x;
    const int lane = tid & 31;
    const int wid  = tid >> 5;
    const int warp_m = wid & 3;       // 0..3 -> 32 rows each
    const int warp_n = wid >> 2;      // 0..3 -> 32 cols each

    const int row0 = blockIdx.y * 128;
    const int col0 = blockIdx.x * 128;

    // A global-load mapping: 128x8 float4, 2 per thread
    const int ar  = tid >> 3;         // 0..63 (rows ar, ar+64)
    const int ac4 = tid & 7;          // float4 column
    // B global-load mapping: 32 k-rows x 16 chunks of 8 halfs, 1 per thread per array
    const int bkr = tid >> 4;         // 0..31
    const int bn8 = tid & 15;         // 0..15

    float4 aReg[2];
    uint4  bRegH, bRegL;

    const int NK = K >> 5;

    float acc[2][4][4];
#pragma unroll
    for (int mt = 0; mt < 2; mt++)
#pragma unroll
        for (int nb = 0; nb < 4; nb++)
#pragma unroll
            for (int j = 0; j < 4; j++) acc[mt][nb][j] = 0.f;

#define LDG_TILE(IT)                                                              \
    {                                                                             \
        int k0 = (IT) * 32;                                                       \
        _Pragma("unroll")                                                         \
        for (int i = 0; i < 2; i++) {                                             \
            int gm = row0 + ar + i * 64;                                          \
            if (gm < M) aReg[i] = *(const float4*)(A + (size_t)gm * K + k0 + ac4 * 4); \
            else        aReg[i] = make_float4(0.f, 0.f, 0.f, 0.f);                \
        }                                                                         \
        size_t boff = (size_t)(k0 + bkr) * N + col0 + bn8 * 8;                    \
        bRegH = *(const uint4*)(Bh + boff);                                       \
        bRegL = *(const uint4*)(Bl + boff);                                       \
    }

#define STS_TILE(ST)                                                              \
    {                                                                             \
        _Pragma("unroll")                                                         \
        for (int i = 0; i < 2; i++) {                                             \
            int r = ar + i * 64;                                                  \
            uint32_t h0, l0, h1, l1;                                              \
            split2(aReg[i].x, aReg[i].y, h0, l0);                                 \
            split2(aReg[i].z, aReg[i].w, h1, l1);                                 \
            uint32_t* ph = (uint32_t*)(sAh + (ST) * SA_STAGE + r * SA_STRIDE + ac4 * 4); \
            uint32_t* pl = (uint32_t*)(sAl + (ST) * SA_STAGE + r * SA_STRIDE + ac4 * 4); \
            ph[0] = h0; ph[1] = h1;                                               \
            pl[0] = l0; pl[1] = l1;                                               \
        }                                                                         \
        *(uint4*)(sBh + (ST) * SB_STAGE + bkr * SB_STRIDE + bn8 * 8) = bRegH;     \
        *(uint4*)(sBl + (ST) * SB_STAGE + bkr * SB_STRIDE + bn8 * 8) = bRegL;     \
    }

    // prologue
    LDG_TILE(0);
    STS_TILE(0);
    if (NK > 1) LDG_TILE(1);
    __syncthreads();

    for (int it = 0; it < NK; ++it) {
        int cur = it & 1;
        if (it + 1 < NK) STS_TILE(cur ^ 1);
        if (it + 2 < NK) LDG_TILE(it + 2);

        // compute on stage `cur`
        const __nv_bfloat16* aH = sAh + cur * SA_STAGE;
        const __nv_bfloat16* aL = sAl + cur * SA_STAGE;
        const __nv_bfloat16* bH = sBh + cur * SB_STAGE;
        const __nv_bfloat16* bL = sBl + cur * SB_STAGE;

#pragma unroll
        for (int ks = 0; ks < 2; ks++) {
            uint32_t ah[2][4], al[2][4], bh[4][2], bl[4][2];
#pragma unroll
            for (int mt = 0; mt < 2; mt++) {
                int row = warp_m * 32 + mt * 16 + (lane & 15);
                int col = ks * 16 + ((lane >> 4) << 3);
                uint32_t adh = (uint32_t)__cvta_generic_to_shared(aH + row * SA_STRIDE + col);
                uint32_t adl = (uint32_t)__cvta_generic_to_shared(aL + row * SA_STRIDE + col);
                ldm_x4(ah[mt][0], ah[mt][1], ah[mt][2], ah[mt][3], adh);
                ldm_x4(al[mt][0], al[mt][1], al[mt][2], al[mt][3], adl);
            }
#pragma unroll
            for (int g = 0; g < 2; g++) {
                int kk = ks * 16 + ((lane >> 3) & 1) * 8 + (lane & 7);
                int nn = warp_n * 32 + g * 16 + ((lane >> 4) & 1) * 8;
                uint32_t adh = (uint32_t)__cvta_generic_to_shared(bH + kk * SB_STRIDE + nn);
                uint32_t adl = (uint32_t)__cvta_generic_to_shared(bL + kk * SB_STRIDE + nn);
                uint32_t r0, r1, r2, r3;
                ldm_x4_trans(r0, r1, r2, r3, adh);
                bh[2 * g][0] = r0; bh[2 * g][1] = r1;
                bh[2 * g + 1][0] = r2; bh[2 * g + 1][1] = r3;
                ldm_x4_trans(r0, r1, r2, r3, adl);
                bl[2 * g][0] = r0; bl[2 * g][1] = r1;
                bl[2 * g + 1][0] = r2; bl[2 * g + 1][1] = r3;
            }
#pragma unroll
            for (int mt = 0; mt < 2; mt++)
#pragma unroll
                for (int nb = 0; nb < 4; nb++) {
                    mma_bf16(acc[mt][nb], ah[mt], bh[nb]);   // hi*hi
                    mma_bf16(acc[mt][nb], ah[mt], bl[nb]);   // hi*lo
                    mma_bf16(acc[mt][nb], al[mt], bh[nb]);   // lo*hi
                }
        }
        __syncthreads();
    }

    // epilogue with bias
#pragma unroll
    for (int mt = 0; mt < 2; mt++) {
#pragma unroll
        for (int nb = 0; nb < 4; nb++) {
            int gn = col0 + warp_n * 32 + nb * 8 + (lane & 3) * 2;
            float b0 = bias[gn], b1 = bias[gn + 1];
            int gm0 = row0 + warp_m * 32 + mt * 16 + (lane >> 2);
            if (gm0 < M) {
                float2 v = make_float2(acc[mt][nb][0] + b0, acc[mt][nb][1] + b1);
                *(float2*)(C + (size_t)gm0 * N + gn) = v;
            }
            int gm1 = gm0 + 8;
            if (gm1 < M) {
                float2 v = make_float2(acc[mt][nb][2] + b0, acc[mt][nb][3] + b1);
                *(float2*)(C + (size_t)gm1 * N + gn) = v;
            }
        }
    }
#undef LDG_TILE
#undef STS_TILE
}

// ---------------- deformable sampling ----------------
// One warp per (b, n, h). Lane i owns sample i (l = i>>3, p = i&7).
__global__ void sample_kernel(const float* __restrict__ ref) {
    int gw = (blockIdx.x * blockDim.x + threadIdx.x) >> 5;
    int lane = threadIdx.x & 31;
    if (gw >= BSZ * NQ * NH) return;

    int h = gw & (NH - 1);
    int n = (gw >> 3) % NQ;
    int b = gw / (NQ * NH);

    int l = lane >> 3;
    int Hs = c_Hs[l], Ws = c_Ws[l];

    long qrow = (long)b * NQ + n;

    int ocol = ((h * NL + l) * NP + (lane & 7)) * 2;
    float ox = g_off[qrow * (NH * NL * NP * 2) + ocol];
    float oy = g_off[qrow * (NH * NL * NP * 2) + ocol + 1];
    float rx = ref[(qrow * NL + l) * 2 + 0];
    float ry = ref[(qrow * NL + l) * 2 + 1];

    float x = rx * (float)Ws + ox - 0.5f;
    float y = ry * (float)Hs + oy - 0.5f;

    float fx0 = floorf(x), fy0 = floorf(y);
    int x0 = (int)fx0, y0 = (int)fy0;
    float wx1 = x - fx0, wy1 = y - fy0;
    float wx0 = 1.f - wx1, wy0 = 1.f - wy1;

    float logit = g_attnl[qrow * EDIM + h * DH + lane];
    float m = logit;
#pragma unroll
    for (int o = 16; o; o >>= 1) m = fmaxf(m, __shfl_xor_sync(0xFFFFFFFFu, m, o));
    float ex = __expf(logit - m);
    float s = ex;
#pragma unroll
    for (int o = 16; o; o >>= 1) s += __shfl_xor_sync(0xFFFFFFFFu, s, o);
    float aw = ex / s;

    int x1 = x0 + 1, y1 = y0 + 1;
    bool vx0 = (x0 >= 0) && (x0 < Ws);
    bool vx1 = (x1 >= 0) && (x1 < Ws);
    bool vy0 = (y0 >= 0) && (y0 < Hs);
    bool vy1 = (y1 >= 0) && (y1 < Hs);

    int base = (b * LEN_VAL + c_start[l]) * EDIM + h * DH;

    int p00 = (vy0 && vx0) ? (y0 * Ws + x0) : 0;
    int p01 = (vy0 && vx1) ? (y0 * Ws + x1) : 0;
    int p10 = (vy1 && vx0) ? (y1 * Ws + x0) : 0;
    int p11 = (vy1 && vx1) ? (y1 * Ws + x1) : 0;

    float w00 = (vy0 && vx0) ? aw * wx0 * wy0 : 0.f;
    float w01 = (vy0 && vx1) ? aw * wx1 * wy0 : 0.f;
    float w10 = (vy1 && vx0) ? aw * wx0 * wy1 : 0.f;
    float w11 = (vy1 && vx1) ? aw * wx1 * wy1 : 0.f;

    int o00 = base + p00 * EDIM;
    int o01 = base + p01 * EDIM;
    int o10 = base + p10 * EDIM;
    int o11 = base + p11 * EDIM;

    float acc = 0.f;
#pragma unroll 4
    for (int sIdx = 0; sIdx < 32; sIdx++) {
        int a0 = __shfl_sync(0xFFFFFFFFu, o00, sIdx);
        int a1 = __shfl_sync(0xFFFFFFFFu, o01, sIdx);
        int a2 = __shfl_sync(0xFFFFFFFFu, o10, sIdx);
        int a3 = __shfl_sync(0xFFFFFFFFu, o11, sIdx);
        float u0 = __shfl_sync(0xFFFFFFFFu, w00, sIdx);
        float u1 = __shfl_sync(0xFFFFFFFFu, w01, sIdx);
        float u2 = __shfl_sync(0xFFFFFFFFu, w10, sIdx);
        float u3 = __shfl_sync(0xFFFFFFFFu, w11, sIdx);
        float v0 = g_v[a0 + lane];
        float v1 = g_v[a1 + lane];
        float v2 = g_v[a2 + lane];
        float v3 = g_v[a3 + lane];
        acc += u0 * v0 + u1 * v1 + u2 * v2 + u3 * v3;
    }
    g_mid[qrow * EDIM + h * DH + lane] = acc;
}

// ---------------- launch ----------------
extern "C" void kernel_launch(void* const* d_in, const int* in_sizes, int n_in,
                              void* d_out, int out_size) {
    const float* query   = (const float*)d_in[0];
    const float* value   = (const float*)d_in[1];
    const float* qpos    = (const float*)d_in[2];
    const float* refpts  = (const float*)d_in[3];
    // d_in[4] = spatial_shapes (compile-time known)
    const float* W_off   = (const float*)d_in[5];
    const float* b_off   = (const float*)d_in[6];
    const float* W_attn  = (const float*)d_in[7];
    const float* b_attn  = (const float*)d_in[8];
    const float* W_val   = (const float*)d_in[9];
    const float* b_val   = (const float*)d_in[10];
    const float* W_out   = (const float*)d_in[11];
    const float* b_out   = (const float*)d_in[12];
    float* out = (float*)d_out;

    float* vq;    cudaGetSymbolAddress((void**)&vq, g_q);
    float* vv;    cudaGetSymbolAddress((void**)&vv, g_v);
    float* voff;  cudaGetSymbolAddress((void**)&voff, g_off);
    float* vattn; cudaGetSymbolAddress((void**)&vattn, g_attnl);
    float* vmid;  cudaGetSymbolAddress((void**)&vmid, g_mid);
    __nv_bfloat16* wh; cudaGetSymbolAddress((void**)&wh, g_Wh);
    __nv_bfloat16* wl; cudaGetSymbolAddress((void**)&wl, g_Wl);

    static bool attr_set = false;
    if (!attr_set) {
        cudaFuncSetAttribute(gemm_bf16x3_kernel,
                             cudaFuncAttributeMaxDynamicSharedMemorySize, GEMM_SMEM);
        attr_set = true;
    }

    // 0) split weights to bf16 hi/lo
    split_weights_kernel<<<(WTOTAL + 255) / 256, 256>>>(W_val, W_off, W_attn, W_out);

    // 1) q = query + query_pos
    {
        int n4 = BSZ * NQ * EDIM / 4;
        add_pos_kernel<<<(n4 + 255) / 256, 256>>>(
            (const float4*)query, (const float4*)qpos, (float4*)vq, n4);
    }
    // 2) v = value @ W_val + b_val
    {
        int M = BSZ * LEN_VAL, N = EDIM, K = EDIM;
        dim3 grid(N / 128, (M + 127) / 128);
        gemm_bf16x3_kernel<<<grid, 512, GEMM_SMEM>>>(
            value, wh + WOFF_VAL, wl + WOFF_VAL, b_val, vv, M, N, K);
    }
    // 3) off = q @ W_off + b_off (N = 512)
    {
        int M = BSZ * NQ, N = NH * NL * NP * 2, K = EDIM;
        dim3 grid(N / 128, (M + 127) / 128);
        gemm_bf16x3_kernel<<<grid, 512, GEMM_SMEM>>>(
            vq, wh + WOFF_OFF, wl + WOFF_OFF, b_off, voff, M, N, K);
    }
    // 4) attn logits = q @ W_attn + b_attn
    {
        int M = BSZ * NQ, N = EDIM, K = EDIM;
        dim3 grid(N / 128, (M + 127) / 128);
        gemm_bf16x3_kernel<<<grid, 512, GEMM_SMEM>>>(
            vq, wh + WOFF_ATTN, wl + WOFF_ATTN, b_attn, vattn, M, N, K);
    }
    // 5) deformable sampling -> g_mid
    {
        int warps = BSZ * NQ * NH;               // 160000
        int blocks = (warps * 32 + 255) / 256;   // 20000
        sample_kernel<<<blocks, 256>>>(refpts);
    }
    // 6) out = g_mid @ W_out + b_out
    {
        int M = BSZ * NQ, N = EDIM, K = EDIM;
        dim3 grid(N / 128, (M + 127) / 128);
        gemm_bf16x3_kernel<<<grid, 512, GEMM_SMEM>>>(
            vmid, wh + WOFF_OUT, wl + WOFF_OUT, b_out, out, M, N, K);
    }
}